// round 16
// baseline (speedup 1.0000x reference)
#include <cuda_runtime.h>
#include <cuda_fp16.h>
#include <cstdint>

#define BB   8192
#define FF   512
#define TT   64
#define NPAD 4096
#define OO   128
#define KA   512      // GEMM1 K (fp16)
#define KP   4096     // GEMM2 K (fp16)
#define NSPLIT 4

// ---------------- scratch (allocation-free rule) ----------------
__device__ __half g_A [(size_t)BB  * KA];   // x       fp16 [8192][512]
__device__ __half g_B1[(size_t)NPAD * KA];  // Wnodes  fp16 [4096][512], row n = t*64+node
__device__ float  g_biasT[NPAD];            // bias, tree-major
__device__ __half g_P [(size_t)BB  * KP];   // prob    fp16 [8192][4096], col k = t*64+leaf
__device__ __half g_W2[(size_t)OO  * KP];   // Wleaf   fp16 [128][4096]
__device__ float  g_part[NSPLIT][(size_t)BB * OO]; // GEMM2 split-K partials

// ---------------- helpers ----------------
__device__ __forceinline__ float smooth_step(float v) {
    float tc = fminf(fmaxf(v, -0.5f), 0.5f);
    return fmaf(tc, fmaf(-2.f, tc * tc, 1.5f), 0.5f);
}

__device__ __forceinline__ uint32_t smem_u32(const void* p) {
    uint32_t a;
    asm("{ .reg .u64 t; cvta.to.shared.u64 t, %1; cvt.u32.u64 %0, t; }" : "=r"(a) : "l"(p));
    return a;
}

__device__ __forceinline__ void cp16(uint32_t sdst, const void* gsrc) {
    asm volatile("cp.async.cg.shared.global [%0], [%1], 16;" :: "r"(sdst), "l"(gsrc));
}
#define CP_COMMIT() asm volatile("cp.async.commit_group;" ::: "memory")
#define CP_WAIT(n)  asm volatile("cp.async.wait_group %0;" :: "n"(n) : "memory")

__device__ __forceinline__ void ldsm4(uint32_t (&r)[4], uint32_t addr) {
    asm volatile("ldmatrix.sync.aligned.m8n8.x4.shared.b16 {%0,%1,%2,%3}, [%4];"
        : "=r"(r[0]), "=r"(r[1]), "=r"(r[2]), "=r"(r[3]) : "r"(addr));
}

__device__ __forceinline__ void mma_fp16(float (&d)[4], const uint32_t (&a)[4],
                                         const uint32_t* b) {
    asm volatile("mma.sync.aligned.m16n8k16.row.col.f32.f16.f16.f32 "
        "{%0,%1,%2,%3}, {%4,%5,%6,%7}, {%8,%9}, {%0,%1,%2,%3};"
        : "+f"(d[0]), "+f"(d[1]), "+f"(d[2]), "+f"(d[3])
        : "r"(a[0]), "r"(a[1]), "r"(a[2]), "r"(a[3]), "r"(b[0]), "r"(b[1]));
}

// ---------------- unified prep kernel ----------------
#define PREP_NA 1024               // x convert, 16 elems/thread (4x float4)
#define PREP_NB (63 * 8)           // W_nodes transpose
#define PREP_NC 128                // W_leaf transpose, one block per o (coalesced)
#define PREP_ND 128                // pad node 63

__global__ __launch_bounds__(256) void prep_all(const float* __restrict__ x,
                                                const float* __restrict__ Wn,
                                                const float* __restrict__ bn,
                                                const float* __restrict__ Wl) {
    __shared__ float tile[64][65];
    int bid = blockIdx.x;
    int tid = threadIdx.x;

    if (bid < PREP_NA) {
        // 4 float4 per thread, MLP-friendly
        int base = bid * 1024 + tid;                       // float4 index
        float4 v[4];
        #pragma unroll
        for (int it = 0; it < 4; it++)
            v[it] = reinterpret_cast<const float4*>(x)[base + it * 256];
        #pragma unroll
        for (int it = 0; it < 4; it++) {
            int idx = base + it * 256;
            reinterpret_cast<__half2*>(g_A)[2 * idx]     = __floats2half2_rn(v[it].x, v[it].y);
            reinterpret_cast<__half2*>(g_A)[2 * idx + 1] = __floats2half2_rn(v[it].z, v[it].w);
        }
        return;
    }
    bid -= PREP_NA;
    if (bid < PREP_NB) {
        int node = bid >> 3;            // 0..62
        int kb   = bid & 7;             // 0..7 (64 k each)
        const float* src = Wn + (size_t)node * (FF * TT) + (size_t)kb * 64 * TT;
        #pragma unroll
        for (int it = 0; it < 16; it++) {
            int idx = tid + it * 256;   // 64*64
            int kl = idx >> 6, t = idx & 63;
            tile[t][kl] = src[kl * TT + t];
        }
        __syncthreads();
        #pragma unroll
        for (int it = 0; it < 16; it++) {
            int idx = tid + it * 256;
            int t = idx >> 6, kl = idx & 63;
            int n = t * 64 + node;
            g_B1[(size_t)n * KA + kb * 64 + kl] = __float2half(tile[t][kl]);
        }
        if (kb == 0 && tid < 64) g_biasT[tid * 64 + node] = bn[node * TT + tid];
        return;
    }
    bid -= PREP_NB;
    if (bid < PREP_NC) {
        // W_leaf transpose for output head o = bid:
        //   g_W2[o][t*64 + l] = Wl[l][o][t]
        int o = bid;
        #pragma unroll
        for (int it = 0; it < 16; it++) {
            int idx = tid + it * 256;   // 64*64, l-major, t contiguous (coalesced read)
            int l = idx >> 6, t = idx & 63;
            tile[l][t] = Wl[(size_t)l * (OO * TT) + (size_t)o * TT + t];
        }
        __syncthreads();
        #pragma unroll
        for (int it = 0; it < 16; it++) {
            int idx = tid + it * 256;   // k = t*64 + l, l contiguous (coalesced write)
            int t = idx >> 6, l = idx & 63;
            g_W2[(size_t)o * KP + t * 64 + l] = __float2half(tile[l][t]);
        }
        return;
    }
    bid -= PREP_NC;
    {
        int idx = bid * 256 + tid;                         // TT*KA
        int t = idx >> 9, k = idx & 511;
        g_B1[(size_t)(t * 64 + 63) * KA + k] = __float2half(0.f);
        if (k == 0) g_biasT[t * 64 + 63] = 0.f;
    }
}

// ---------------- mma.sync fp16 GEMM (4-stage cp.async pipeline) ----------------
// C[m][n] = sum_k A[m,k]*B[n,k], fp16 inputs, fp32 accum. Chunk = 32 K-elems.
// smem row = 64B (32 fp16), XOR swizzle: 16B-chunk' = chunk ^ ((row>>1)&3).
template<int BM, int BN, int WM, int WN, int WGN, int MAXB, bool TREE>
__global__ void __launch_bounds__(256, MAXB)
mma_gemm(const __half* __restrict__ A, const __half* __restrict__ B,
         const float* __restrict__ bias, float* __restrict__ outp,
         int ldA, int ldB, int nchunk, int chunks_per_split) {
    constexpr int STAGE = (BM + BN) * 64;              // bytes
    constexpr int MI = WM / 16, NI = WN / 8;
    extern __shared__ char smem[];
    const uint32_t sb = smem_u32(smem);

    const int tid = threadIdx.x, wid = tid >> 5, lane = tid & 31;
    const int wm = wid / WGN, wn = wid % WGN;
    const int m0 = blockIdx.y * BM, n0 = blockIdx.x * BN;
    const int kbase = blockIdx.z * chunks_per_split;
    if (!TREE) outp += (size_t)blockIdx.z * BB * OO;

    // lane-invariant ldmatrix address pieces
    const int laneRow = ((lane >> 3) & 1) * 8 + (lane & 7);
    const int laneC2  = lane >> 4;
    const int xorp    = (laneRow >> 1) & 3;

    auto load_stage = [&](int s, int c) {
        uint32_t st = sb + s * STAGE;
        #pragma unroll
        for (int j = 0; j < BM * 4 / 256; j++) {
            int idx = tid + j * 256;
            int row = idx >> 2, cc = idx & 3;
            uint32_t dst = st + row * 64 + ((cc ^ ((row >> 1) & 3)) << 4);
            cp16(dst, reinterpret_cast<const char*>(
                A + (size_t)(m0 + row) * ldA + c * 32) + cc * 16);
        }
        #pragma unroll
        for (int j = 0; j < BN * 4 / 256; j++) {
            int idx = tid + j * 256;
            int row = idx >> 2, cc = idx & 3;
            uint32_t dst = st + BM * 64 + row * 64 + ((cc ^ ((row >> 1) & 3)) << 4);
            cp16(dst, reinterpret_cast<const char*>(
                B + (size_t)(n0 + row) * ldB + c * 32) + cc * 16);
        }
    };

    float acc[MI][NI][4];
    #pragma unroll
    for (int i = 0; i < MI; i++)
        #pragma unroll
        for (int j = 0; j < NI; j++)
            #pragma unroll
            for (int q = 0; q < 4; q++) acc[i][j][q] = 0.f;

    uint32_t rowA[MI], rowB[NI / 2];
    #pragma unroll
    for (int i = 0; i < MI; i++) rowA[i] = (uint32_t)(wm * WM + i * 16 + laneRow) * 64;
    #pragma unroll
    for (int j2 = 0; j2 < NI / 2; j2++)
        rowB[j2] = (uint32_t)(wn * WN + j2 * 16 + laneRow) * 64;

    load_stage(0, kbase);     CP_COMMIT();
    load_stage(1, kbase + 1); CP_COMMIT();
    load_stage(2, kbase + 2); CP_COMMIT();

    #pragma unroll 1
    for (int c = 0; c < nchunk; c++) {
        CP_WAIT(2);
        __syncthreads();
        // issue next load before the MMA burst; targets stage (c+3)&3 == (c-1)&3,
        // whose consumers all passed the barrier above.
        if (c + 3 < nchunk) load_stage((c + 3) & 3, kbase + c + 3);
        CP_COMMIT();

        const uint32_t aS = sb + (c & 3) * STAGE;
        const uint32_t bS = aS + BM * 64;
        #pragma unroll
        for (int ks = 0; ks < 2; ks++) {
            const int c2 = ks * 2;
            const uint32_t swoff = (uint32_t)(((c2 + laneC2) ^ xorp) << 4);
            uint32_t bfrag[NI][2];
            #pragma unroll
            for (int j2 = 0; j2 < NI / 2; j2++) {
                uint32_t t4[4];
                ldsm4(t4, bS + rowB[j2] + swoff);
                bfrag[2 * j2][0] = t4[0]; bfrag[2 * j2 + 1][0] = t4[1];
                bfrag[2 * j2][1] = t4[2]; bfrag[2 * j2 + 1][1] = t4[3];
            }
            #pragma unroll
            for (int i = 0; i < MI; i++) {
                uint32_t afrag[4];
                ldsm4(afrag, aS + rowA[i] + swoff);
                #pragma unroll
                for (int j = 0; j < NI; j++) mma_fp16(acc[i][j], afrag, bfrag[j]);
            }
        }
    }
    CP_WAIT(0);
    __syncthreads();

    if (TREE) {
        constexpr int SST = BN + 1;                    // sbuf row stride (floats)
        float bv[NI][2];
        #pragma unroll
        for (int j = 0; j < NI; j++) {
            int cc = n0 + wn * WN + j * 8 + (lane & 3) * 2;
            bv[j][0] = bias[cc];
            bv[j][1] = bias[cc + 1];
        }
        // stage s = smooth_step(acc + bias) into smem [BM][SST]
        float* sbuf = reinterpret_cast<float*>(smem);
        #pragma unroll
        for (int i = 0; i < MI; i++) {
            #pragma unroll
            for (int j = 0; j < NI; j++) {
                int r0 = wm * WM + i * 16 + (lane >> 2);
                int cc = wn * WN + j * 8 + (lane & 3) * 2;
                sbuf[r0 * SST + cc]           = smooth_step(acc[i][j][0] + bv[j][0]);
                sbuf[r0 * SST + cc + 1]       = smooth_step(acc[i][j][1] + bv[j][1]);
                sbuf[(r0 + 8) * SST + cc]     = smooth_step(acc[i][j][2] + bv[j][0]);
                sbuf[(r0 + 8) * SST + cc + 1] = smooth_step(acc[i][j][3] + bv[j][1]);
            }
        }
        __syncthreads();

        // tree expansion: (row, tree-group)
        {
            int row = tid & (BM - 1), tg = tid / BM;
            float* srow = sbuf + row * SST + tg * 64;
            float p[64];
            p[0] = 1.f;
            int base = 0;
            #pragma unroll
            for (int lvl = 0; lvl < 6; lvl++) {
                int width = 1 << lvl;
                #pragma unroll
                for (int i = width - 1; i >= 0; i--) {
                    float sv = srow[base + i];
                    float pi = p[i];
                    p[2 * i]     = pi * sv;
                    p[2 * i + 1] = pi * (1.f - sv);
                }
                base += width;
            }
            #pragma unroll
            for (int l = 0; l < 64; l++) srow[l] = p[l];
        }
        __syncthreads();

        // coalesced fp16 emit: BM*(BN/2) half2 over 256 threads
        constexpr int PAIRS = BN / 2;
        #pragma unroll
        for (int it = 0; it < BM * PAIRS / 256; it++) {
            int idx = tid + it * 256;
            int row = idx / PAIRS, cpair = idx % PAIRS;
            __half2 hv = __floats2half2_rn(sbuf[row * SST + 2 * cpair],
                                           sbuf[row * SST + 2 * cpair + 1]);
            reinterpret_cast<__half2*>(g_P + (size_t)(m0 + row) * KP + n0)[cpair] = hv;
        }
    } else {
        #pragma unroll
        for (int i = 0; i < MI; i++) {
            #pragma unroll
            for (int j = 0; j < NI; j++) {
                int r0 = m0 + wm * WM + i * 16 + (lane >> 2);
                int cc = n0 + wn * WN + j * 8 + (lane & 3) * 2;
                *reinterpret_cast<float2*>(outp + (size_t)r0 * OO + cc) =
                    make_float2(acc[i][j][0], acc[i][j][1]);
                *reinterpret_cast<float2*>(outp + (size_t)(r0 + 8) * OO + cc) =
                    make_float2(acc[i][j][2], acc[i][j][3]);
            }
        }
    }
}

// Sum the split-K partials into d_out (deterministic order).
// 4 float4 per thread per partial -> 16 loads in flight (MLP).
__global__ void reduce_parts(float* __restrict__ out) {
    int base = (blockIdx.x * blockDim.x + threadIdx.x) * 4;     // float4 index
    float4 a[4], b[4], c[4], d[4];
    #pragma unroll
    for (int q = 0; q < 4; q++) a[q] = reinterpret_cast<const float4*>(g_part[0])[base + q];
    #pragma unroll
    for (int q = 0; q < 4; q++) b[q] = reinterpret_cast<const float4*>(g_part[1])[base + q];
    #pragma unroll
    for (int q = 0; q < 4; q++) c[q] = reinterpret_cast<const float4*>(g_part[2])[base + q];
    #pragma unroll
    for (int q = 0; q < 4; q++) d[q] = reinterpret_cast<const float4*>(g_part[3])[base + q];
    #pragma unroll
    for (int q = 0; q < 4; q++) {
        float4 r;
        r.x = (a[q].x + b[q].x) + (c[q].x + d[q].x);
        r.y = (a[q].y + b[q].y) + (c[q].y + d[q].y);
        r.z = (a[q].z + b[q].z) + (c[q].z + d[q].z);
        r.w = (a[q].w + b[q].w) + (c[q].w + d[q].w);
        reinterpret_cast<float4*>(out)[base + q] = r;
    }
}

// ---------------- launch ----------------
extern "C" void kernel_launch(void* const* d_in, const int* in_sizes, int n_in,
                              void* d_out, int out_size) {
    const float* x  = (const float*)d_in[0];
    const float* Wn = (const float*)d_in[1];
    const float* bn = (const float*)d_in[2];
    const float* Wl = (const float*)d_in[3];

    void *pA, *pB1, *pBias, *pP, *pW2, *pPart;
    cudaGetSymbolAddress(&pA, g_A);
    cudaGetSymbolAddress(&pB1, g_B1);
    cudaGetSymbolAddress(&pBias, g_biasT);
    cudaGetSymbolAddress(&pP, g_P);
    cudaGetSymbolAddress(&pW2, g_W2);
    cudaGetSymbolAddress(&pPart, g_part);

    // GEMM1: BM=128, BN=128, WM=64, WN=32, 2 CTAs/SM
    //   smem = max(4 stages x 16KB = 64KB, epilogue 128*129*4 = 66048)
    constexpr int SM1 = 128 * 129 * 4;
    // GEMM2: BM=128, BN=128, WM=64, WN=32, 2 CTAs/SM; 4 stages x 16KB
    constexpr int SM2 = 4 * (128 + 128) * 64;

    cudaFuncSetAttribute((const void*)mma_gemm<128, 128, 64, 32, 4, 2, true>,
                         cudaFuncAttributeMaxDynamicSharedMemorySize, SM1);
    cudaFuncSetAttribute((const void*)mma_gemm<128, 128, 64, 32, 4, 2, false>,
                         cudaFuncAttributeMaxDynamicSharedMemorySize, SM2);

    prep_all<<<PREP_NA + PREP_NB + PREP_NC + PREP_ND, 256>>>(x, Wn, bn, Wl);

    // GEMM1 + fused bias/smooth_step/tree-expansion/fp16 emit
    mma_gemm<128, 128, 64, 32, 4, 2, true>
        <<<dim3(NPAD / 128, BB / 128, 1), 256, SM1>>>(
        (const __half*)pA, (const __half*)pB1,
        (const float*)pBias, nullptr, KA, KA, 16, 0);

    // GEMM2 split-K x4: part[z][b,o] = sum_{k in split z} P[b,k] W2[o,k]
    mma_gemm<128, 128, 64, 32, 4, 2, false>
        <<<dim3(1, BB / 128, NSPLIT), 256, SM2>>>(
        (const __half*)pP, (const __half*)pW2,
        nullptr, (float*)pPart, KP, KP, 32, 32);

    reduce_parts<<<(BB * OO / 16) / 256, 256>>>((float*)d_out);
}

// round 17
// speedup vs baseline: 1.0023x; 1.0023x over previous
#include <cuda_runtime.h>
#include <cuda_fp16.h>
#include <cstdint>

#define BB   8192
#define FF   512
#define TT   64
#define NPAD 4096
#define OO   128
#define KA   512      // GEMM1 K (fp16)
#define KP   4096     // GEMM2 K (fp16)
#define NSPLIT 4

// ---------------- scratch (allocation-free rule) ----------------
__device__ __half g_A [(size_t)BB  * KA];   // x       fp16 [8192][512]
__device__ __half g_B1[(size_t)NPAD * KA];  // Wnodes  fp16 [4096][512], row n = t*64+node
__device__ float  g_biasT[NPAD];            // bias, tree-major
__device__ __half g_P [(size_t)BB  * KP];   // prob    fp16 [8192][4096], col k = t*64+leaf
__device__ __half g_W2[(size_t)OO  * KP];   // Wleaf   fp16 [128][4096]
__device__ float  g_part[NSPLIT][(size_t)BB * OO]; // GEMM2 split-K partials

// ---------------- helpers ----------------
__device__ __forceinline__ float smooth_step(float v) {
    float tc = fminf(fmaxf(v, -0.5f), 0.5f);
    return fmaf(tc, fmaf(-2.f, tc * tc, 1.5f), 0.5f);
}

__device__ __forceinline__ uint32_t smem_u32(const void* p) {
    uint32_t a;
    asm("{ .reg .u64 t; cvta.to.shared.u64 t, %1; cvt.u32.u64 %0, t; }" : "=r"(a) : "l"(p));
    return a;
}

__device__ __forceinline__ void cp16(uint32_t sdst, const void* gsrc) {
    asm volatile("cp.async.cg.shared.global [%0], [%1], 16;" :: "r"(sdst), "l"(gsrc));
}
#define CP_COMMIT() asm volatile("cp.async.commit_group;" ::: "memory")
#define CP_WAIT(n)  asm volatile("cp.async.wait_group %0;" :: "n"(n) : "memory")

__device__ __forceinline__ void ldsm4(uint32_t (&r)[4], uint32_t addr) {
    asm volatile("ldmatrix.sync.aligned.m8n8.x4.shared.b16 {%0,%1,%2,%3}, [%4];"
        : "=r"(r[0]), "=r"(r[1]), "=r"(r[2]), "=r"(r[3]) : "r"(addr));
}

__device__ __forceinline__ void mma_fp16(float (&d)[4], const uint32_t (&a)[4],
                                         const uint32_t* b) {
    asm volatile("mma.sync.aligned.m16n8k16.row.col.f32.f16.f16.f32 "
        "{%0,%1,%2,%3}, {%4,%5,%6,%7}, {%8,%9}, {%0,%1,%2,%3};"
        : "+f"(d[0]), "+f"(d[1]), "+f"(d[2]), "+f"(d[3])
        : "r"(a[0]), "r"(a[1]), "r"(a[2]), "r"(a[3]), "r"(b[0]), "r"(b[1]));
}

// ---------------- unified prep kernel ----------------
#define PREP_NA 4096               // x convert, 4 elems/thread (float4)
#define PREP_NB (63 * 8)           // W_nodes transpose
#define PREP_NC 2048               // W_leaf convert
#define PREP_ND 128                // pad node 63

__global__ __launch_bounds__(256) void prep_all(const float* __restrict__ x,
                                                const float* __restrict__ Wn,
                                                const float* __restrict__ bn,
                                                const float* __restrict__ Wl) {
    __shared__ float tile[64][65];
    int bid = blockIdx.x;
    int tid = threadIdx.x;

    if (bid < PREP_NA) {
        int idx = bid * 256 + tid;                         // BB*FF/4
        float4 v = reinterpret_cast<const float4*>(x)[idx];
        __half2 h0 = __floats2half2_rn(v.x, v.y);
        __half2 h1 = __floats2half2_rn(v.z, v.w);
        reinterpret_cast<__half2*>(g_A)[2 * idx]     = h0;
        reinterpret_cast<__half2*>(g_A)[2 * idx + 1] = h1;
        return;
    }
    bid -= PREP_NA;
    if (bid < PREP_NB) {
        int node = bid >> 3;            // 0..62
        int kb   = bid & 7;             // 0..7 (64 k each)
        const float* src = Wn + (size_t)node * (FF * TT) + (size_t)kb * 64 * TT;
        #pragma unroll
        for (int it = 0; it < 16; it++) {
            int idx = tid + it * 256;   // 64*64
            int kl = idx >> 6, t = idx & 63;
            tile[t][kl] = src[kl * TT + t];
        }
        __syncthreads();
        #pragma unroll
        for (int it = 0; it < 16; it++) {
            int idx = tid + it * 256;
            int t = idx >> 6, kl = idx & 63;
            int n = t * 64 + node;
            g_B1[(size_t)n * KA + kb * 64 + kl] = __float2half(tile[t][kl]);
        }
        if (kb == 0 && tid < 64) g_biasT[tid * 64 + node] = bn[node * TT + tid];
        return;
    }
    bid -= PREP_NB;
    if (bid < PREP_NC) {
        int idx = bid * 256 + tid;                         // OO*NPAD
        int o = idx >> 12, k = idx & 4095;
        int t = k >> 6, l = k & 63;
        g_W2[(size_t)o * KP + k] =
            __float2half(Wl[(size_t)l * (OO * TT) + (size_t)o * TT + t]);
        return;
    }
    bid -= PREP_NC;
    {
        int idx = bid * 256 + tid;                         // TT*KA
        int t = idx >> 9, k = idx & 511;
        g_B1[(size_t)(t * 64 + 63) * KA + k] = __float2half(0.f);
        if (k == 0) g_biasT[t * 64 + 63] = 0.f;
    }
}

// ---------------- mma.sync fp16 GEMM (4-stage cp.async pipeline) ----------------
// C[m][n] = sum_k A[m,k]*B[n,k], fp16 inputs, fp32 accum. Chunk = 32 K-elems.
// smem row = 64B (32 fp16), XOR swizzle: 16B-chunk' = chunk ^ ((row>>1)&3).
template<int BM, int BN, int WM, int WN, int WGN, int MAXB, bool TREE>
__global__ void __launch_bounds__(256, MAXB)
mma_gemm(const __half* __restrict__ A, const __half* __restrict__ B,
         const float* __restrict__ bias, float* __restrict__ outp,
         int ldA, int ldB, int nchunk, int chunks_per_split) {
    constexpr int STAGE = (BM + BN) * 64;              // bytes
    constexpr int MI = WM / 16, NI = WN / 8;
    extern __shared__ char smem[];
    const uint32_t sb = smem_u32(smem);

    const int tid = threadIdx.x, wid = tid >> 5, lane = tid & 31;
    const int wm = wid / WGN, wn = wid % WGN;
    const int m0 = blockIdx.y * BM, n0 = blockIdx.x * BN;
    const int kbase = blockIdx.z * chunks_per_split;
    if (!TREE) outp += (size_t)blockIdx.z * BB * OO;

    // lane-invariant ldmatrix address pieces
    const int laneRow = ((lane >> 3) & 1) * 8 + (lane & 7);
    const int laneC2  = lane >> 4;
    const int xorp    = (laneRow >> 1) & 3;

    auto load_stage = [&](int s, int c) {
        uint32_t st = sb + s * STAGE;
        #pragma unroll
        for (int j = 0; j < BM * 4 / 256; j++) {
            int idx = tid + j * 256;
            int row = idx >> 2, cc = idx & 3;
            uint32_t dst = st + row * 64 + ((cc ^ ((row >> 1) & 3)) << 4);
            cp16(dst, reinterpret_cast<const char*>(
                A + (size_t)(m0 + row) * ldA + c * 32) + cc * 16);
        }
        #pragma unroll
        for (int j = 0; j < BN * 4 / 256; j++) {
            int idx = tid + j * 256;
            int row = idx >> 2, cc = idx & 3;
            uint32_t dst = st + BM * 64 + row * 64 + ((cc ^ ((row >> 1) & 3)) << 4);
            cp16(dst, reinterpret_cast<const char*>(
                B + (size_t)(n0 + row) * ldB + c * 32) + cc * 16);
        }
    };

    float acc[MI][NI][4];
    #pragma unroll
    for (int i = 0; i < MI; i++)
        #pragma unroll
        for (int j = 0; j < NI; j++)
            #pragma unroll
            for (int q = 0; q < 4; q++) acc[i][j][q] = 0.f;

    uint32_t rowA[MI], rowB[NI / 2];
    #pragma unroll
    for (int i = 0; i < MI; i++) rowA[i] = (uint32_t)(wm * WM + i * 16 + laneRow) * 64;
    #pragma unroll
    for (int j2 = 0; j2 < NI / 2; j2++)
        rowB[j2] = (uint32_t)(wn * WN + j2 * 16 + laneRow) * 64;

    load_stage(0, kbase);     CP_COMMIT();
    load_stage(1, kbase + 1); CP_COMMIT();
    load_stage(2, kbase + 2); CP_COMMIT();

    #pragma unroll 1
    for (int c = 0; c < nchunk; c++) {
        CP_WAIT(2);
        __syncthreads();
        // issue next load before the MMA burst; targets stage (c+3)&3 == (c-1)&3,
        // whose consumers all passed the barrier above.
        if (c + 3 < nchunk) load_stage((c + 3) & 3, kbase + c + 3);
        CP_COMMIT();

        const uint32_t aS = sb + (c & 3) * STAGE;
        const uint32_t bS = aS + BM * 64;
        #pragma unroll
        for (int ks = 0; ks < 2; ks++) {
            const int c2 = ks * 2;
            const uint32_t swoff = (uint32_t)(((c2 + laneC2) ^ xorp) << 4);
            uint32_t bfrag[NI][2];
            #pragma unroll
            for (int j2 = 0; j2 < NI / 2; j2++) {
                uint32_t t4[4];
                ldsm4(t4, bS + rowB[j2] + swoff);
                bfrag[2 * j2][0] = t4[0]; bfrag[2 * j2 + 1][0] = t4[1];
                bfrag[2 * j2][1] = t4[2]; bfrag[2 * j2 + 1][1] = t4[3];
            }
            #pragma unroll
            for (int i = 0; i < MI; i++) {
                uint32_t afrag[4];
                ldsm4(afrag, aS + rowA[i] + swoff);
                #pragma unroll
                for (int j = 0; j < NI; j++) mma_fp16(acc[i][j], afrag, bfrag[j]);
            }
        }
    }
    CP_WAIT(0);
    __syncthreads();

    if (TREE) {
        constexpr int SST = BN + 1;                    // sbuf row stride (floats)
        float bv[NI][2];
        #pragma unroll
        for (int j = 0; j < NI; j++) {
            int cc = n0 + wn * WN + j * 8 + (lane & 3) * 2;
            bv[j][0] = bias[cc];
            bv[j][1] = bias[cc + 1];
        }
        // stage s = smooth_step(acc + bias) into smem [BM][SST]
        float* sbuf = reinterpret_cast<float*>(smem);
        #pragma unroll
        for (int i = 0; i < MI; i++) {
            #pragma unroll
            for (int j = 0; j < NI; j++) {
                int r0 = wm * WM + i * 16 + (lane >> 2);
                int cc = wn * WN + j * 8 + (lane & 3) * 2;
                sbuf[r0 * SST + cc]           = smooth_step(acc[i][j][0] + bv[j][0]);
                sbuf[r0 * SST + cc + 1]       = smooth_step(acc[i][j][1] + bv[j][1]);
                sbuf[(r0 + 8) * SST + cc]     = smooth_step(acc[i][j][2] + bv[j][0]);
                sbuf[(r0 + 8) * SST + cc + 1] = smooth_step(acc[i][j][3] + bv[j][1]);
            }
        }
        __syncthreads();

        // tree expansion: (row, tree-group)
        {
            int row = tid & (BM - 1), tg = tid / BM;
            float* srow = sbuf + row * SST + tg * 64;
            float p[64];
            p[0] = 1.f;
            int base = 0;
            #pragma unroll
            for (int lvl = 0; lvl < 6; lvl++) {
                int width = 1 << lvl;
                #pragma unroll
                for (int i = width - 1; i >= 0; i--) {
                    float sv = srow[base + i];
                    float pi = p[i];
                    p[2 * i]     = pi * sv;
                    p[2 * i + 1] = pi * (1.f - sv);
                }
                base += width;
            }
            #pragma unroll
            for (int l = 0; l < 64; l++) srow[l] = p[l];
        }
        __syncthreads();

        // coalesced fp16 emit: BM*(BN/2) half2 over 256 threads
        constexpr int PAIRS = BN / 2;
        #pragma unroll
        for (int it = 0; it < BM * PAIRS / 256; it++) {
            int idx = tid + it * 256;
            int row = idx / PAIRS, cpair = idx % PAIRS;
            __half2 hv = __floats2half2_rn(sbuf[row * SST + 2 * cpair],
                                           sbuf[row * SST + 2 * cpair + 1]);
            reinterpret_cast<__half2*>(g_P + (size_t)(m0 + row) * KP + n0)[cpair] = hv;
        }
    } else {
        #pragma unroll
        for (int i = 0; i < MI; i++) {
            #pragma unroll
            for (int j = 0; j < NI; j++) {
                int r0 = m0 + wm * WM + i * 16 + (lane >> 2);
                int cc = n0 + wn * WN + j * 8 + (lane & 3) * 2;
                *reinterpret_cast<float2*>(outp + (size_t)r0 * OO + cc) =
                    make_float2(acc[i][j][0], acc[i][j][1]);
                *reinterpret_cast<float2*>(outp + (size_t)(r0 + 8) * OO + cc) =
                    make_float2(acc[i][j][2], acc[i][j][3]);
            }
        }
    }
}

// Sum the split-K partials into d_out (deterministic order).
__global__ void reduce_parts(float* __restrict__ out) {
    int idx = blockIdx.x * blockDim.x + threadIdx.x;            // BB*OO/4
    float4 a = reinterpret_cast<const float4*>(g_part[0])[idx];
    float4 b = reinterpret_cast<const float4*>(g_part[1])[idx];
    float4 c = reinterpret_cast<const float4*>(g_part[2])[idx];
    float4 d = reinterpret_cast<const float4*>(g_part[3])[idx];
    float4 r;
    r.x = (a.x + b.x) + (c.x + d.x);
    r.y = (a.y + b.y) + (c.y + d.y);
    r.z = (a.z + b.z) + (c.z + d.z);
    r.w = (a.w + b.w) + (c.w + d.w);
    reinterpret_cast<float4*>(out)[idx] = r;
}

// ---------------- launch ----------------
extern "C" void kernel_launch(void* const* d_in, const int* in_sizes, int n_in,
                              void* d_out, int out_size) {
    const float* x  = (const float*)d_in[0];
    const float* Wn = (const float*)d_in[1];
    const float* bn = (const float*)d_in[2];
    const float* Wl = (const float*)d_in[3];

    void *pA, *pB1, *pBias, *pP, *pW2, *pPart;
    cudaGetSymbolAddress(&pA, g_A);
    cudaGetSymbolAddress(&pB1, g_B1);
    cudaGetSymbolAddress(&pBias, g_biasT);
    cudaGetSymbolAddress(&pP, g_P);
    cudaGetSymbolAddress(&pW2, g_W2);
    cudaGetSymbolAddress(&pPart, g_part);

    // GEMM1: BM=128, BN=128, WM=64, WN=32, 2 CTAs/SM
    //   smem = max(4 stages x 16KB = 64KB, epilogue 128*129*4 = 66048)
    constexpr int SM1 = 128 * 129 * 4;
    // GEMM2: BM=128, BN=128, WM=64, WN=32, 2 CTAs/SM; 4 stages x 16KB
    constexpr int SM2 = 4 * (128 + 128) * 64;

    cudaFuncSetAttribute((const void*)mma_gemm<128, 128, 64, 32, 4, 2, true>,
                         cudaFuncAttributeMaxDynamicSharedMemorySize, SM1);
    cudaFuncSetAttribute((const void*)mma_gemm<128, 128, 64, 32, 4, 2, false>,
                         cudaFuncAttributeMaxDynamicSharedMemorySize, SM2);

    prep_all<<<PREP_NA + PREP_NB + PREP_NC + PREP_ND, 256>>>(x, Wn, bn, Wl);

    // GEMM1 + fused bias/smooth_step/tree-expansion/fp16 emit
    mma_gemm<128, 128, 64, 32, 4, 2, true>
        <<<dim3(NPAD / 128, BB / 128, 1), 256, SM1>>>(
        (const __half*)pA, (const __half*)pB1,
        (const float*)pBias, nullptr, KA, KA, 16, 0);

    // GEMM2 split-K x4: part[z][b,o] = sum_{k in split z} P[b,k] W2[o,k]
    mma_gemm<128, 128, 64, 32, 4, 2, false>
        <<<dim3(1, BB / 128, NSPLIT), 256, SM2>>>(
        (const __half*)pP, (const __half*)pW2,
        nullptr, (float*)pPart, KP, KP, 32, 32);

    reduce_parts<<<(BB * OO / 4) / 256, 256>>>((float*)d_out);
}